// round 17
// baseline (speedup 1.0000x reference)
#include <cuda_runtime.h>
#include <cuda_bf16.h>
#include <cstdint>

#define EPSF 1e-6f
#define ONE_M_EPS (1.0f - 1e-6f)
#define NEG_LOG_EPS 13.815510557964274f      /* -log(1e-6)   */
#define NEG_LOG_1ME 1.0000005000002918e-06f  /* -log(1-1e-6) */
#define INV_TEMP 14.285714285714285f         /* 1/0.07       */

// ---------------- device scratch ----------------
__device__ float d_qk[8u * 1024u * 1024u];     // 32 MB sim matrix (qk dot products)
__device__ float d_rsum[8192], d_rsq[8192], d_rse[8192];   // per (b,l), reduced over s
__device__ float d_csum[8192], d_csq[8192], d_cse[8192];   // per (b,s), reduced over l
__device__ unsigned d_rmaxu[8192], d_cmaxu[8192];          // order-preserving-key float max
__device__ float d_sharp1[8192], d_sharp2[8192];
__device__ float d_rlog[8192], d_clog[8192];   // log sum exp denominators
__device__ double d_acc[8][8];   // per-b: 0 poscnt,1 negcnt,2 geopos,3 geoneg,4 loss1,5 loss2,6 loss3
__device__ double d_cacc[2];     // contrastive: pos sum, neg sum

// ---------------- helpers ----------------
__device__ __forceinline__ float warpSum(float v) {
#pragma unroll
    for (int o = 16; o > 0; o >>= 1) v += __shfl_down_sync(0xffffffffu, v, o);
    return v;
}
__device__ __forceinline__ float warpMax(float v) {
#pragma unroll
    for (int o = 16; o > 0; o >>= 1) v = fmaxf(v, __shfl_down_sync(0xffffffffu, v, o));
    return v;
}
__device__ __forceinline__ unsigned fkey(float f) {
    unsigned b = __float_as_uint(f);
    return (b & 0x80000000u) ? ~b : (b | 0x80000000u);
}
__device__ __forceinline__ float funkey(unsigned u) {
    return __uint_as_float((u & 0x80000000u) ? (u ^ 0x80000000u) : ~u);
}
__device__ __forceinline__ void ldsm4(unsigned addr, unsigned& r0, unsigned& r1,
                                      unsigned& r2, unsigned& r3) {
    asm volatile("ldmatrix.sync.aligned.m8n8.x4.shared.b16 {%0,%1,%2,%3}, [%4];"
                 : "=r"(r0), "=r"(r1), "=r"(r2), "=r"(r3) : "r"(addr));
}
__device__ __forceinline__ void mma_bf16(float& c0, float& c1, float& c2, float& c3,
                                         unsigned a0, unsigned a1, unsigned a2, unsigned a3,
                                         unsigned b0, unsigned b1) {
    asm volatile(
        "mma.sync.aligned.m16n8k16.row.col.f32.bf16.bf16.f32 "
        "{%0,%1,%2,%3}, {%4,%5,%6,%7}, {%8,%9}, {%0,%1,%2,%3};"
        : "+f"(c0), "+f"(c1), "+f"(c2), "+f"(c3)
        : "r"(a0), "r"(a1), "r"(a2), "r"(a3), "r"(b0), "r"(b1));
}
// split fp32 -> (hi, lo) bf16 pair; x - float(hi) is exact (Sterbenz)
__device__ __forceinline__ void cvsplit(__nv_bfloat16* hi, __nv_bfloat16* lo,
                                        int off, float4 v) {
    __nv_bfloat16 h0 = __float2bfloat16(v.x), h1 = __float2bfloat16(v.y);
    __nv_bfloat16 h2 = __float2bfloat16(v.z), h3 = __float2bfloat16(v.w);
    __nv_bfloat16 l0 = __float2bfloat16(v.x - __bfloat162float(h0));
    __nv_bfloat16 l1 = __float2bfloat16(v.y - __bfloat162float(h1));
    __nv_bfloat16 l2 = __float2bfloat16(v.z - __bfloat162float(h2));
    __nv_bfloat16 l3 = __float2bfloat16(v.w - __bfloat162float(h3));
    *reinterpret_cast<__nv_bfloat162*>(hi + off)     = __nv_bfloat162(h0, h1);
    *reinterpret_cast<__nv_bfloat162*>(hi + off + 2) = __nv_bfloat162(h2, h3);
    *reinterpret_cast<__nv_bfloat162*>(lo + off)     = __nv_bfloat162(l0, l1);
    *reinterpret_cast<__nv_bfloat162*>(lo + off + 2) = __nv_bfloat162(l2, l3);
}

// ---------------- zero accumulators ----------------
__global__ void k_zero() {
    int i = blockIdx.x * 1024 + threadIdx.x;
    if (i < 8192) {
        d_rsum[i] = 0.f; d_rsq[i] = 0.f; d_rse[i] = 0.f; d_rmaxu[i] = 0u;
        d_csum[i] = 0.f; d_csq[i] = 0.f; d_cse[i] = 0.f; d_cmaxu[i] = 0u;
    }
    if (i < 64) ((double*)d_acc)[i] = 0.0;
    if (i < 2) d_cacc[i] = 0.0;
}

// ---------------- tensor-core GEMM (split-bf16 x3) + fused stats ----------------
// d_qk[b,l,s] = sum_c q[b,l,c]*k[b,s,c] via mma.sync m16n8k16 bf16:
// x = qh*kh + qh*kl + ql*kh (fp32 accum), |err| ~ 5e-7.
// Tile 128x128 per CTA, 256 thr, warp = 32m x 64n (2 m-frags x 8 n-frags).
// K chunked by 64; smem = A/B hi+lo bf16 [128][72] (pad 8 => conflict-free ldsm).
#define LDK 72
__global__ __launch_bounds__(256, 2) void k_gemm(const float* __restrict__ Q,
                                                 const float* __restrict__ Kp) {
    extern __shared__ __nv_bfloat16 smraw[];
    __nv_bfloat16* Ah = smraw;
    __nv_bfloat16* Al = Ah + 128 * LDK;
    __nv_bfloat16* Bh = Al + 128 * LDK;
    __nv_bfloat16* Bl = Bh + 128 * LDK;

    int b = blockIdx.z;
    int l0 = blockIdx.y * 128;
    int s0 = blockIdx.x * 128;
    const float* Qb = Q + (size_t)b * 1024 * 128;
    const float* Kb = Kp + (size_t)b * 1024 * 128;
    int tid = threadIdx.x;
    int w = tid >> 5, ln = tid & 31;
    int wm = w >> 1, wn = w & 1;          // warp rows 32*wm, cols 64*wn
    int g = ln >> 2, t4 = ln & 3;

    unsigned baseAh = (unsigned)__cvta_generic_to_shared(Ah);
    unsigned baseAl = (unsigned)__cvta_generic_to_shared(Al);
    unsigned baseBh = (unsigned)__cvta_generic_to_shared(Bh);
    unsigned baseBl = (unsigned)__cvta_generic_to_shared(Bl);

    int part = ln >> 3;
    int rowA = 32 * wm + ((part & 1) << 3) + (ln & 7);   // + 16*mb
    int kofA = (part >> 1) << 3;                          // + ks*16
    int rowB = 64 * wn + ((part >> 1) << 3) + (ln & 7);   // + 16*nfp
    int kofB = (part & 1) << 3;

    float cf[2][8][4];
#pragma unroll
    for (int mb = 0; mb < 2; mb++)
#pragma unroll
        for (int nf = 0; nf < 8; nf++)
#pragma unroll
            for (int r = 0; r < 4; r++) cf[mb][nf][r] = 0.f;

#pragma unroll
    for (int kc = 0; kc < 2; kc++) {
        if (kc) __syncthreads();
        // load fp32 chunk + split-convert to bf16 hi/lo in smem
#pragma unroll
        for (int it = 0; it < 8; it++) {
            int lin = tid + 256 * it;
            int row = lin >> 4, c4 = lin & 15;
            float4 va = *(const float4*)(Qb + (size_t)(l0 + row) * 128 + kc * 64 + c4 * 4);
            cvsplit(Ah, Al, row * LDK + c4 * 4, va);
            float4 vb = *(const float4*)(Kb + (size_t)(s0 + row) * 128 + kc * 64 + c4 * 4);
            cvsplit(Bh, Bl, row * LDK + c4 * 4, vb);
        }
        __syncthreads();
#pragma unroll
        for (int ks = 0; ks < 4; ks++) {
            unsigned aH[2][4], aL[2][4];
#pragma unroll
            for (int mb = 0; mb < 2; mb++) {
                unsigned off = (unsigned)(((rowA + 16 * mb) * LDK + ks * 16 + kofA) * 2);
                ldsm4(baseAh + off, aH[mb][0], aH[mb][1], aH[mb][2], aH[mb][3]);
                ldsm4(baseAl + off, aL[mb][0], aL[mb][1], aL[mb][2], aL[mb][3]);
            }
#pragma unroll
            for (int nfp = 0; nfp < 4; nfp++) {
                unsigned off = (unsigned)(((rowB + 16 * nfp) * LDK + ks * 16 + kofB) * 2);
                unsigned bh0, bh1, bh2, bh3, bl0, bl1, bl2, bl3;
                ldsm4(baseBh + off, bh0, bh1, bh2, bh3);
                ldsm4(baseBl + off, bl0, bl1, bl2, bl3);
#pragma unroll
                for (int mb = 0; mb < 2; mb++) {
                    float* c0 = cf[mb][2 * nfp];
                    float* c1 = cf[mb][2 * nfp + 1];
                    mma_bf16(c0[0], c0[1], c0[2], c0[3],
                             aH[mb][0], aH[mb][1], aH[mb][2], aH[mb][3], bh0, bh1);
                    mma_bf16(c0[0], c0[1], c0[2], c0[3],
                             aH[mb][0], aH[mb][1], aH[mb][2], aH[mb][3], bl0, bl1);
                    mma_bf16(c0[0], c0[1], c0[2], c0[3],
                             aL[mb][0], aL[mb][1], aL[mb][2], aL[mb][3], bh0, bh1);
                    mma_bf16(c1[0], c1[1], c1[2], c1[3],
                             aH[mb][0], aH[mb][1], aH[mb][2], aH[mb][3], bh2, bh3);
                    mma_bf16(c1[0], c1[1], c1[2], c1[3],
                             aH[mb][0], aH[mb][1], aH[mb][2], aH[mb][3], bl2, bl3);
                    mma_bf16(c1[0], c1[1], c1[2], c1[3],
                             aL[mb][0], aL[mb][1], aL[mb][2], aL[mb][3], bh2, bh3);
                }
            }
        }
    }

    // ---- fused stats epilogue on fragment layout ----
    // thread value (mb,nf,pr,j): row = l0+32wm+16mb+8pr+g, col = s0+64wn+8nf+2t4+j
    float rs_sum[2][2], rs_sq[2][2], rs_se[2][2], rs_mx[2][2];
#pragma unroll
    for (int mb = 0; mb < 2; mb++)
#pragma unroll
        for (int pr = 0; pr < 2; pr++) {
            rs_sum[mb][pr] = 0.f; rs_sq[mb][pr] = 0.f;
            rs_se[mb][pr] = 0.f; rs_mx[mb][pr] = -1e30f;
        }
#pragma unroll
    for (int nf = 0; nf < 8; nf++) {
        float cs_sum[2] = {0.f, 0.f}, cs_sq[2] = {0.f, 0.f};
        float cs_se[2] = {0.f, 0.f}, cs_mx[2] = {-1e30f, -1e30f};
#pragma unroll
        for (int mb = 0; mb < 2; mb++) {
#pragma unroll
            for (int pr = 0; pr < 2; pr++) {
#pragma unroll
                for (int j = 0; j < 2; j++) {
                    float x = cf[mb][nf][2 * pr + j];
                    float e = expf(x * INV_TEMP);
                    rs_sum[mb][pr] += x; rs_sq[mb][pr] = fmaf(x, x, rs_sq[mb][pr]);
                    rs_se[mb][pr] += e; rs_mx[mb][pr] = fmaxf(rs_mx[mb][pr], x);
                    cs_sum[j] += x; cs_sq[j] = fmaf(x, x, cs_sq[j]);
                    cs_se[j] += e; cs_mx[j] = fmaxf(cs_mx[j], x);
                }
                int gr = l0 + 32 * wm + 16 * mb + 8 * pr + g;
                int gc = s0 + 64 * wn + 8 * nf + 2 * t4;
                *(float2*)(d_qk + ((size_t)(b * 1024 + gr) << 10) + gc) =
                    make_float2(cf[mb][nf][2 * pr], cf[mb][nf][2 * pr + 1]);
            }
        }
        // col reduce across the 8 g-lanes
#pragma unroll
        for (int o = 4; o < 32; o <<= 1) {
#pragma unroll
            for (int j = 0; j < 2; j++) {
                cs_sum[j] += __shfl_xor_sync(0xffffffffu, cs_sum[j], o);
                cs_sq[j]  += __shfl_xor_sync(0xffffffffu, cs_sq[j], o);
                cs_se[j]  += __shfl_xor_sync(0xffffffffu, cs_se[j], o);
                cs_mx[j] = fmaxf(cs_mx[j], __shfl_xor_sync(0xffffffffu, cs_mx[j], o));
            }
        }
        if (ln < 4) {
#pragma unroll
            for (int j = 0; j < 2; j++) {
                int col = b * 1024 + s0 + 64 * wn + 8 * nf + 2 * ln + j;
                atomicAdd(&d_csum[col], cs_sum[j]);
                atomicAdd(&d_csq[col], cs_sq[j]);
                atomicAdd(&d_cse[col], cs_se[j]);
                atomicMax(&d_cmaxu[col], fkey(cs_mx[j]));
            }
        }
    }
    // row reduce across the 4 t4-lanes
#pragma unroll
    for (int o = 1; o < 4; o <<= 1) {
#pragma unroll
        for (int mb = 0; mb < 2; mb++)
#pragma unroll
            for (int pr = 0; pr < 2; pr++) {
                rs_sum[mb][pr] += __shfl_xor_sync(0xffffffffu, rs_sum[mb][pr], o);
                rs_sq[mb][pr]  += __shfl_xor_sync(0xffffffffu, rs_sq[mb][pr], o);
                rs_se[mb][pr]  += __shfl_xor_sync(0xffffffffu, rs_se[mb][pr], o);
                rs_mx[mb][pr] = fmaxf(rs_mx[mb][pr], __shfl_xor_sync(0xffffffffu, rs_mx[mb][pr], o));
            }
    }
    if (t4 == 0) {
#pragma unroll
        for (int mb = 0; mb < 2; mb++)
#pragma unroll
            for (int pr = 0; pr < 2; pr++) {
                int row = b * 1024 + l0 + 32 * wm + 16 * mb + 8 * pr + g;
                atomicAdd(&d_rsum[row], rs_sum[mb][pr]);
                atomicAdd(&d_rsq[row], rs_sq[mb][pr]);
                atomicAdd(&d_rse[row], rs_se[mb][pr]);
                atomicMax(&d_rmaxu[row], fkey(rs_mx[mb][pr]));
            }
    }
}

// ---------------- sharpness softmax (merged row+col; 16 blocks x 1024) ----------------
__global__ __launch_bounds__(1024) void k_sharp(float* __restrict__ out) {
    __shared__ float sh[32];
    int which = blockIdx.x >> 3;   // 0 = row (l over s), 1 = col (s over l)
    int b = blockIdx.x & 7;
    const float* smp = which ? d_csum : d_rsum;
    const float* sqp = which ? d_csq : d_rsq;
    const float* sep = which ? d_cse : d_rse;
    const unsigned* mxp = which ? d_cmaxu : d_rmaxu;
    float* sharp = which ? d_sharp1 : d_sharp2;
    float* lse = which ? d_clog : d_rlog;
    int i = b * 1024 + threadIdx.x;
    float smv = smp[i];
    float mean = smv * (1.f / 1024.f);
    float var = (sqp[i] - smv * smv * (1.f / 1024.f)) * (1.f / 1023.f);
    float sv = (funkey(mxp[i]) - mean) / sqrtf(fmaxf(var, 1e-30f));
    lse[i] = logf(sep[i]);
    int lane = threadIdx.x & 31, w = threadIdx.x >> 5;
    float m = warpMax(sv);
    if (lane == 0) sh[w] = m;
    __syncthreads();
    if (w == 0) { float x = sh[lane]; x = warpMax(x); if (lane == 0) sh[0] = x; }
    __syncthreads();
    float M = sh[0];
    __syncthreads();
    float e = expf(sv - M);
    float s = warpSum(e);
    if (lane == 0) sh[w] = s;
    __syncthreads();
    if (w == 0) { float x = sh[lane]; x = warpSum(x); if (lane == 0) sh[0] = x; }
    __syncthreads();
    float S = sh[0];
    float o = e / S;
    sharp[i] = o;
    if (which) out[i] = o;   // sharpness output = sharp1
}

// ---------------- main masked accumulation over (b,l,s) ----------------
__global__ __launch_bounds__(256) void k_main(const int* __restrict__ label) {
    int b = blockIdx.y;
    int l0 = blockIdx.x * 8;
    int w = threadIdx.x >> 5;
    int lane = threadIdx.x & 31;
    int row = b * 1024 + l0 + w;
    const float4* qrow = (const float4*)(d_qk + (size_t)row * 1024);
    const int4* lrow = (const int4*)(label + (size_t)row * 1024);
    const float4* clog4 = (const float4*)(d_clog + b * 1024);
    const float4* sh14 = (const float4*)(d_sharp1 + b * 1024);
    float logrs = d_rlog[row];
    float sh2 = d_sharp2[row];
    const float C0 = -logf(1.0f - 1e-6f);
    const float T_LO = -13.815510557964274f;

    float poscnt = 0.f, negcnt = 0.f, gp = 0.f, gn = 0.f, L1 = 0.f, NLL = 0.f, L3 = 0.f;
#pragma unroll 4
    for (int k2 = 0; k2 < 8; k2++) {
        int idx = lane + 32 * k2;
        float4 xv = qrow[idx];
        int4 lv = lrow[idx];
        float4 cv = clog4[idx];
        float4 w1 = sh14[idx];
        float xs[4] = {xv.x, xv.y, xv.z, xv.w};
        int lb[4] = {lv.x, lv.y, lv.z, lv.w};
        float cs[4] = {cv.x, cv.y, cv.z, cv.w};
        float ws[4] = {w1.x, w1.y, w1.z, w1.w};
#pragma unroll
        for (int j = 0; j < 4; j++) {
            float x = xs[j];
            float t = fmaf(2.f * INV_TEMP, x, -cs[j] - logrs);
            float simc = fminf(fmaxf((1.f + x) * 0.5f, EPSF), ONE_M_EPS);
            if (lb[j] == 1) {
                poscnt += 1.f;
                gp += fminf(fmaxf(-t, NEG_LOG_1ME), NEG_LOG_EPS);
                float nll = -__logf(simc);
                L1 = fmaf(nll, ws[j], L1);
                NLL += nll;
            } else {
                negcnt += 1.f;
                if (t < T_LO) {
                    gn += C0;
                } else {
                    float conf = fminf(__expf(t), ONE_M_EPS);
                    float y = 1.0f - conf;
                    float d = 1.0f - y;
                    if (d < 0.05f) {
                        gn += d * fmaf(d, fmaf(d, fmaf(d, 0.25f, 0.33333334f), 0.5f), 1.0f);
                    } else {
                        gn -= logf(y);
                    }
                }
                float y3 = 1.0f - simc;
                L3 -= __logf(y3);
            }
        }
    }
    poscnt = warpSum(poscnt); negcnt = warpSum(negcnt);
    gp = warpSum(gp); gn = warpSum(gn);
    L1 = warpSum(L1); NLL = warpSum(NLL); L3 = warpSum(L3);
    __shared__ float sh[8][7];
    if (lane == 0) {
        sh[w][0] = poscnt; sh[w][1] = negcnt; sh[w][2] = gp; sh[w][3] = gn;
        sh[w][4] = L1; sh[w][5] = sh2 * NLL; sh[w][6] = L3;
    }
    __syncthreads();
    if (threadIdx.x < 7) {
        int k = threadIdx.x;
        float a = sh[0][k];
#pragma unroll
        for (int j = 1; j < 8; j++) a += sh[j][k];
        atomicAdd(&d_acc[b][k], (double)a);
    }
}

// ---------------- contrastive branch ----------------
__global__ __launch_bounds__(256) void k_cl(const float* __restrict__ q_cl,
                                            const float* __restrict__ cl_pos,
                                            const int* __restrict__ idx) {
    __shared__ float qn[8][128];
    __shared__ int sidx[8];
    int tid = threadIdx.x;
    if (tid < 8) sidx[tid] = idx[tid];
    __syncthreads();
    int w = tid >> 5, lane = tid & 31;
    {
        const float* qp = q_cl + ((size_t)w * 256 + sidx[w]) * 128;
        float4 v = ((const float4*)qp)[lane];
        float ss = v.x * v.x + v.y * v.y + v.z * v.z + v.w * v.w;
#pragma unroll
        for (int o = 16; o > 0; o >>= 1) ss += __shfl_xor_sync(0xffffffffu, ss, o);
        float inv = 1.f / fmaxf(sqrtf(ss), 1e-12f);
        ((float4*)&qn[w][0])[lane] = make_float4(v.x * inv, v.y * inv, v.z * inv, v.w * inv);
    }
    __syncthreads();
    int r = blockIdx.x * 256 + tid;
    const float* kp;
    if (r < 8) {
        kp = cl_pos + ((size_t)r * 256 + sidx[r]) * 128;
    } else {
        int rr = r - 8;
        int n = rr / 255;
        int j = rr % 255 + 1;
        int jj = (j == sidx[n]) ? 0 : j;
        kp = cl_pos + ((size_t)n * 256 + jj) * 128;
    }
    float dot[8] = {0.f, 0.f, 0.f, 0.f, 0.f, 0.f, 0.f, 0.f};
    float ksq = 0.f;
    const float4* kp4 = (const float4*)kp;
#pragma unroll 8
    for (int c = 0; c < 32; c++) {
        float4 kv = kp4[c];
        ksq = fmaf(kv.x, kv.x, fmaf(kv.y, kv.y, fmaf(kv.z, kv.z, fmaf(kv.w, kv.w, ksq))));
#pragma unroll
        for (int q = 0; q < 8; q++) {
            float4 qv = ((const float4*)qn[q])[c];
            dot[q] = fmaf(kv.x, qv.x, fmaf(kv.y, qv.y, fmaf(kv.z, qv.z, fmaf(kv.w, qv.w, dot[q]))));
        }
    }
    float kinv = 1.f / fmaxf(sqrtf(ksq), 1e-12f);
    float negsum = 0.f;
    if (r < 8) {
        float sim = fminf(fmaxf((1.f + dot[r] * kinv) * 0.5f, EPSF), ONE_M_EPS);
        atomicAdd(&d_cacc[0], (double)(-logf(sim)));
    } else {
#pragma unroll
        for (int q = 0; q < 8; q++) {
            float sim = fminf(fmaxf((1.f + dot[q] * kinv) * 0.5f, EPSF), ONE_M_EPS);
            float y = 1.0f - sim;
            negsum -= logf(y);
        }
    }
    __shared__ float sred[8];
    negsum = warpSum(negsum);
    if (lane == 0) sred[w] = negsum;
    __syncthreads();
    if (tid == 0) {
        float a = sred[0];
#pragma unroll
        for (int j = 1; j < 8; j++) a += sred[j];
        atomicAdd(&d_cacc[1], (double)a);
    }
}

// ---------------- finalize scalars + cl_pos_save ----------------
__global__ __launch_bounds__(1024) void k_final(const float* __restrict__ cl_pos,
                                                const int* __restrict__ idx,
                                                float* __restrict__ out) {
    int tid = threadIdx.x;
    int n = tid >> 7, c = tid & 127;
    out[8192 + tid] = cl_pos[((size_t)n * 256 + idx[n]) * 128 + c];
    if (tid == 0) {
        double gp = 0.0, gn = 0.0, ls = 0.0;
        for (int b = 0; b < 8; b++) {
            double pc = d_acc[b][0]; if (pc < 1.0) pc = 1.0;
            double nc = d_acc[b][1]; if (nc < 1.0) nc = 1.0;
            gp += d_acc[b][2] / pc;
            gn += d_acc[b][3] / nc;
            ls += 0.5 * (d_acc[b][4] + d_acc[b][5]) + d_acc[b][6] / nc;
        }
        gp *= 0.125; gn *= 0.125; ls *= 0.125;
        double loss_geo = gp + gn;
        double geo_comb = (0.5 * loss_geo + 0.5 * ls) * 0.5;
        double contrast = (d_cacc[0] * (1.0 / 8.0) + d_cacc[1] * (1.0 / 16320.0)) * 0.5;
        double lcl = contrast * 0.5;
        out[9216] = (float)(geo_comb + lcl);
        out[9217] = (float)gp;
        out[9218] = (float)gn;
        out[9219] = (float)ls;
        out[9220] = (float)lcl;
    }
}

extern "C" void kernel_launch(void* const* d_in, const int* in_sizes, int n_in,
                              void* d_out, int out_size) {
    const float* q_geo   = (const float*)d_in[0];
    const float* q_cl    = (const float*)d_in[1];
    const float* geo_pos = (const float*)d_in[2];
    const float* cl_pos  = (const float*)d_in[3];
    const int*   label   = (const int*)d_in[4];
    const int*   idx     = (const int*)d_in[5];
    float* out = (float*)d_out;

    static bool attr_done = false;
    if (!attr_done) {
        cudaFuncSetAttribute(k_gemm, cudaFuncAttributeMaxDynamicSharedMemorySize,
                             4 * 128 * LDK * (int)sizeof(__nv_bfloat16));
        attr_done = true;
    }

    k_zero<<<8, 1024>>>();
    k_gemm<<<dim3(8, 8, 8), 256, 4 * 128 * LDK * sizeof(__nv_bfloat16)>>>(q_geo, geo_pos);
    k_sharp<<<16, 1024>>>(out);
    k_main<<<dim3(128, 8), 256>>>(label);
    k_cl<<<8, 256>>>(q_cl, cl_pos, idx);
    k_final<<<1, 1024>>>(cl_pos, idx, out);
}